// round 16
// baseline (speedup 1.0000x reference)
#include <cuda_runtime.h>
#include <cuda_fp16.h>
#include <math.h>
#include <stdint.h>

// ---------------- problem constants ----------------
#define NQ      21760          // num queries == num keys
#define EMBED   256
#define NH      8
#define NL      4
#define NP      4
#define KDIM    256            // K for all GEMMs

__device__ __constant__ int c_start[NL] = {0, 16384, 20480, 21504};
__device__ __constant__ int c_HW[NL]    = {128, 64, 32, 16};   // square levels

// ---------------- scratch (device globals; no allocations allowed) --------
// x-paired value buffer: per (key, head): [x0: 32ch (64B) | x1: 32ch (64B)].
__device__ uint32_t g_pv   [NQ * 256];
__device__ __half   g_oah  [NQ * 384];   // [offsets(256) | logits(128)] fp16
__device__ __half   g_samph[NQ * 256];   // sampled fp16 (feeds out-GEMM)
__device__ __half   g_v16  [NQ * 256];   // value fp16
__device__ __half   g_q16  [NQ * 256];   // (query+query_pos) fp16
__device__ __half   g_wv16 [256 * 256];  // W_value fp16
__device__ __half   g_wcat16[384 * 256]; // concat W_off;W_attn fp16
__device__ __half   g_wout16[256 * 256]; // W_out fp16
__device__ float    g_bcat [384];        // concat b_off;b_attn fp32

// ---------------- prep: fp16 conversions + weight concat ----------------
__device__ __forceinline__ uint32_t pack2(float x, float y) {
    __half2 h = __floats2half2_rn(x, y);
    return *reinterpret_cast<uint32_t*>(&h);
}
__device__ __forceinline__ uint4 cvt8(const float* s) {
    float4 a = *reinterpret_cast<const float4*>(s);
    float4 b = *reinterpret_cast<const float4*>(s + 4);
    return make_uint4(pack2(a.x,a.y), pack2(a.z,a.w), pack2(b.x,b.y), pack2(b.z,b.w));
}
__device__ __forceinline__ uint4 cvt8sum(const float* s, const float* t) {
    float4 a = *reinterpret_cast<const float4*>(s);
    float4 b = *reinterpret_cast<const float4*>(s + 4);
    float4 c = *reinterpret_cast<const float4*>(t);
    float4 d = *reinterpret_cast<const float4*>(t + 4);
    a.x+=c.x; a.y+=c.y; a.z+=c.z; a.w+=c.w;
    b.x+=d.x; b.y+=d.y; b.z+=d.z; b.w+=d.w;
    return make_uint4(pack2(a.x,a.y), pack2(a.z,a.w), pack2(b.x,b.y), pack2(b.z,b.w));
}

#define NV8 (NQ * 256 / 8)   // 696320

__global__ void __launch_bounds__(256) prep_kernel(
    const float* __restrict__ query, const float* __restrict__ query_pos,
    const float* __restrict__ value,
    const float* __restrict__ Wv, const float* __restrict__ Woff,
    const float* __restrict__ Wattn, const float* __restrict__ Wout,
    const float* __restrict__ boff, const float* __restrict__ battn)
{
    int idx = blockIdx.x * 256 + threadIdx.x;
    const int r0 = NV8;                 // value
    const int r1 = 2 * NV8;             // q
    const int r2 = r1 + 8192;           // Wv
    const int r3 = r2 + 12288;          // Wcat
    const int r4 = r3 + 8192;           // Wout
    const int r5 = r4 + 48;             // bcat

    if (idx < r0) {
        reinterpret_cast<uint4*>(g_v16)[idx] = cvt8(value + (size_t)idx * 8);
    } else if (idx < r1) {
        int i = idx - r0;
        reinterpret_cast<uint4*>(g_q16)[i] =
            cvt8sum(query + (size_t)i * 8, query_pos + (size_t)i * 8);
    } else if (idx < r2) {
        int i = idx - r1;
        reinterpret_cast<uint4*>(g_wv16)[i] = cvt8(Wv + (size_t)i * 8);
    } else if (idx < r3) {
        int i = idx - r2;
        int e = i * 8;
        reinterpret_cast<uint4*>(g_wcat16)[i] =
            (e < 65536) ? cvt8(Woff + e) : cvt8(Wattn + (e - 65536));
    } else if (idx < r4) {
        int i = idx - r3;
        reinterpret_cast<uint4*>(g_wout16)[i] = cvt8(Wout + (size_t)i * 8);
    } else if (idx < r5) {
        int i = idx - r4;
        int e = i * 8;
        #pragma unroll
        for (int jj = 0; jj < 8; jj++) {
            int n = e + jj;
            g_bcat[n] = (n < 256) ? boff[n] : battn[n - 256];
        }
    }
}

// ---------------- fp16 HMMA GEMM, 128x64 tile, cp.async 3-stage ----------
#define GBM 128
#define GBN 64
#define GBK 64
#define GS  3
#define NCH (KDIM / GBK)      // 4
#define STAGE_B 24576         // A 16KB + W 8KB
#define W_OFF   16384

__device__ __forceinline__ void cp16(uint32_t dst, const void* src) {
    asm volatile("cp.async.cg.shared.global [%0], [%1], 16;" :: "r"(dst), "l"(src));
}
__device__ __forceinline__ void cp_commit() {
    asm volatile("cp.async.commit_group;");
}
template <int n>
__device__ __forceinline__ void cp_wait() {
    asm volatile("cp.async.wait_group %0;" :: "n"(n));
}
__device__ __forceinline__ void ldsm_x4a(uint32_t* r, uint32_t addr) {
    asm volatile("ldmatrix.sync.aligned.m8n8.x4.shared.b16 {%0,%1,%2,%3}, [%4];"
                 : "=r"(r[0]), "=r"(r[1]), "=r"(r[2]), "=r"(r[3]) : "r"(addr));
}
__device__ __forceinline__ void mma_f16(float* c, const uint32_t* a,
                                        uint32_t b0, uint32_t b1) {
    asm volatile(
        "mma.sync.aligned.m16n8k16.row.col.f32.f16.f16.f32 "
        "{%0,%1,%2,%3}, {%4,%5,%6,%7}, {%8,%9}, {%0,%1,%2,%3};"
        : "+f"(c[0]), "+f"(c[1]), "+f"(c[2]), "+f"(c[3])
        : "r"(a[0]), "r"(a[1]), "r"(a[2]), "r"(a[3]), "r"(b0), "r"(b1));
}

extern __shared__ __half smx[];

__device__ __forceinline__ uint32_t swadr(uint32_t base, int row, int hc) {
    return base + (uint32_t)(row * 64 + ((hc ^ (row & 7)) << 3)) * 2;
}

__global__ void __launch_bounds__(256, 3) gemm_dual(
    const __half* __restrict__ A0, const __half* __restrict__ W0,
    const float* __restrict__ b0, int N0,
    uint32_t* __restrict__ pair0, __half* __restrict__ h0,
    float* __restrict__ f0, const float* __restrict__ id0,
    const __half* __restrict__ A1, const __half* __restrict__ W1,
    const float* __restrict__ b1, int N1,
    uint32_t* __restrict__ pair1, __half* __restrict__ h1,
    float* __restrict__ f1, const float* __restrict__ id1,
    int split)
{
    int bx = blockIdx.x;
    const int by = blockIdx.y;
    const __half *Ag, *Wg; const float* bias; int N;
    uint32_t* Cpair; __half* Ch; float* Cf; const float* ident;
    if (bx < split) {
        Ag = A0; Wg = W0; bias = b0; N = N0;
        Cpair = pair0; Ch = h0; Cf = f0; ident = id0;
    } else {
        bx -= split;
        Ag = A1; Wg = W1; bias = b1; N = N1;
        Cpair = pair1; Ch = h1; Cf = f1; ident = id1;
    }

    const int tid  = threadIdx.x;
    const int warp = tid >> 5;
    const int lane = tid & 31;
    const int g    = lane >> 2;
    const int tig  = lane & 3;
    const int wm   = (warp >> 1) * 32;   // 4 M-groups of 32
    const int wn   = (warp & 1) * 32;    // 2 N-groups of 32
    const int lrow16 = lane & 15;
    const int lk8    = (lane >> 4) << 3;

    const uint32_t sbase = (uint32_t)__cvta_generic_to_shared(smx);

    const int lr = tid >> 3;     // 0..31
    const int cc = tid & 7;      // 16B chunk in 128B slice
    const __half* Abase = Ag + (size_t)(by * GBM) * KDIM;
    const __half* Wbase = Wg + (size_t)(bx * GBN) * KDIM;

    auto load_stage = [&](int st, int kc) {
        const uint32_t sa = sbase + st * STAGE_B;
        const int k0 = kc * GBK;
        #pragma unroll
        for (int r4 = 0; r4 < 4; r4++) {
            int row = r4 * 32 + lr;
            cp16(swadr(sa, row, cc), Abase + (size_t)row * KDIM + k0 + cc * 8);
        }
        #pragma unroll
        for (int r2 = 0; r2 < 2; r2++) {
            int row = r2 * 32 + lr;
            cp16(swadr(sa + W_OFF, row, cc), Wbase + (size_t)row * KDIM + k0 + cc * 8);
        }
        cp_commit();
    };

    float acc[2][4][4];
    #pragma unroll
    for (int i = 0; i < 2; i++)
        #pragma unroll
        for (int jx = 0; jx < 4; jx++)
            #pragma unroll
            for (int t = 0; t < 4; t++) acc[i][jx][t] = 0.f;

    load_stage(0, 0);
    load_stage(1, 1);

    #pragma unroll
    for (int i = 0; i < NCH; i++) {
        if (i < NCH - 1) cp_wait<1>(); else cp_wait<0>();
        __syncthreads();
        const int st = i % GS;
        const uint32_t sa = sbase + st * STAGE_B;

        #pragma unroll
        for (int kk = 0; kk < GBK; kk += 16) {
            const int hc = (kk + lk8) >> 3;
            uint32_t af[2][4];
            #pragma unroll
            for (int mf = 0; mf < 2; mf++)
                ldsm_x4a(af[mf], swadr(sa, wm + mf * 16 + lrow16, hc));
            uint32_t bf[4][2];
            #pragma unroll
            for (int g4 = 0; g4 < 2; g4++) {
                uint32_t r[4];
                ldsm_x4a(r, swadr(sa + W_OFF, wn + g4 * 16 + lrow16, hc));
                bf[g4 * 2 + 0][0] = r[0]; bf[g4 * 2 + 0][1] = r[2];
                bf[g4 * 2 + 1][0] = r[1]; bf[g4 * 2 + 1][1] = r[3];
            }
            #pragma unroll
            for (int mf = 0; mf < 2; mf++)
                #pragma unroll
                for (int nf = 0; nf < 4; nf++)
                    mma_f16(acc[mf][nf], af[mf], bf[nf][0], bf[nf][1]);
        }
        if (i + GS - 1 < NCH) load_stage((i + GS - 1) % GS, i + GS - 1);
    }

    // ---------------- epilogue ----------------
    const int nb = bx * GBN + wn;
    if (Cpair) {
        // staged coalesced pair epilogue: pack to smem (pitch 36 words), then
        // write x0/x1 64B groups with 4 lanes each (full-sector stores).
        uint32_t* stg = reinterpret_cast<uint32_t*>(smx);
        __syncthreads();   // pipeline smem now dead for all warps
        #pragma unroll
        for (int mf = 0; mf < 2; mf++) {
            #pragma unroll
            for (int hh = 0; hh < 2; hh++) {
                int ml = wm + mf * 16 + g + hh * 8;
                #pragma unroll
                for (int nf = 0; nf < 4; nf++) {
                    int col = nb + nf * 8 + tig * 2;   // within N (bias idx)
                    float2 bb = *reinterpret_cast<const float2*>(bias + col);
                    float rx = acc[mf][nf][hh * 2 + 0] + bb.x;
                    float ry = acc[mf][nf][hh * 2 + 1] + bb.y;
                    int cl = (wn + nf * 8 + tig * 2) >> 1;   // 0..31 pair idx
                    stg[ml * 36 + cl] = pack2(rx, ry);
                }
            }
        }
        __syncthreads();
        #pragma unroll
        for (int ro = 0; ro < 4; ro++) {
            int gid  = ro * 64 + (tid >> 2);   // 0..255: (m row, hd half)
            int part = tid & 3;
            int ml = gid >> 1, hdl = gid & 1;
            uint4 val = *reinterpret_cast<uint4*>(&stg[ml * 36 + hdl * 16 + part * 4]);
            int mg = by * GBM + ml;
            int hd = bx * 2 + hdl;
            reinterpret_cast<uint4*>(Cpair + ((size_t)mg * 8 + hd) * 32)[part] = val;
            if (mg > 0)
                reinterpret_cast<uint4*>(
                    Cpair + ((size_t)(mg - 1) * 8 + hd) * 32 + 16)[part] = val;
        }
    } else {
        #pragma unroll
        for (int mf = 0; mf < 2; mf++) {
            #pragma unroll
            for (int hh = 0; hh < 2; hh++) {
                int m = by * GBM + wm + mf * 16 + g + hh * 8;
                #pragma unroll
                for (int nf = 0; nf < 4; nf++) {
                    int col = nb + nf * 8 + tig * 2;
                    float2 bb = *reinterpret_cast<const float2*>(bias + col);
                    float2 r;
                    r.x = acc[mf][nf][hh * 2 + 0] + bb.x;
                    r.y = acc[mf][nf][hh * 2 + 1] + bb.y;
                    if (ident) {
                        float2 iv = *reinterpret_cast<const float2*>(
                            ident + (size_t)m * N + col);
                        r.x += iv.x; r.y += iv.y;
                    }
                    if (Ch) {
                        *reinterpret_cast<__half2*>(Ch + (size_t)m * N + col) =
                            __floats2half2_rn(r.x, r.y);
                    } else {
                        *reinterpret_cast<float2*>(Cf + (size_t)m * N + col) = r;
                    }
                }
            }
        }
    }
}

// ---------------- deformable sampling + fused softmax ----------------
// Warp per (q, head-quad): 8 lanes/head; j<4 accumulate x0-slot, j>=4 x1-slot.
// Lane j owns points 2j, 2j+1. Packed broadcasts: keys (k0|k1<<16) in one u32,
// coefficient (CA,CB) pairs as half2 — 3 shuffles + 2 PRMT per point.
// Inner accumulation in fp16 (HFMA2), drained to fp32 once per level.
__global__ void __launch_bounds__(256) sample_kernel(
    const uint4* __restrict__ pv4, const float* __restrict__ ref,
    const __half* __restrict__ oah, uint4* __restrict__ samp4)
{
    const int gwarp = (blockIdx.x * blockDim.x + threadIdx.x) >> 5;
    const int lane = threadIdx.x & 31;
    if (gwarp >= NQ * 2) return;
    const int q  = gwarp >> 1;
    const int hq = gwarp & 1;
    const int h4 = lane >> 3;
    const int j  = lane & 7;
    const int h  = hq * 4 + h4;
    const bool isA = (j < 4);
    const uint32_t psel = isA ? 0x1010u : 0x3232u;   // PRMT: replicate lo/hi half

    uint2 ov = *reinterpret_cast<const uint2*>(oah + (size_t)q * 384 + h * 32 + j * 4);
    float2 o0 = __half22float2(*reinterpret_cast<__half2*>(&ov.x));
    float2 o1 = __half22float2(*reinterpret_cast<__half2*>(&ov.y));
    uint32_t lvu = *reinterpret_cast<const uint32_t*>(
        oah + (size_t)q * 384 + 256 + h * 16 + j * 2);
    float2 lg = __half22float2(*reinterpret_cast<__half2*>(&lvu));

    float mx = fmaxf(lg.x, lg.y);
    mx = fmaxf(mx, __shfl_xor_sync(0xffffffffu, mx, 1));
    mx = fmaxf(mx, __shfl_xor_sync(0xffffffffu, mx, 2));
    mx = fmaxf(mx, __shfl_xor_sync(0xffffffffu, mx, 4));
    float e0 = __expf(lg.x - mx), e1 = __expf(lg.y - mx);
    float s = e0 + e1;
    s += __shfl_xor_sync(0xffffffffu, s, 1);
    s += __shfl_xor_sync(0xffffffffu, s, 2);
    s += __shfl_xor_sync(0xffffffffu, s, 4);
    float inv = 1.f / s;
    float w0 = e0 * inv, w1 = e1 * inv;

    // owner precompute for owned points 2j (t=0), 2j+1 (t=1)
    uint32_t KK[2], CC0[2], CC1[2];
    #pragma unroll
    for (int t = 0; t < 2; t++) {
        int ptm = 2 * j + t;
        int lvl = ptm >> 2;
        int HW = c_HW[lvl];
        int start = c_start[lvl];
        float fHW = (float)HW;
        float rx = ref[(size_t)q * 8 + lvl * 2 + 0];
        float ry = ref[(size_t)q * 8 + lvl * 2 + 1];
        float ox = t ? o1.x : o0.x;
        float oy = t ? o1.y : o0.y;
        float aw = t ? w1 : w0;

        float gx = fmaf(rx, fHW, ox - 0.5f);
        float gy = fmaf(ry, fHW, oy - 0.5f);
        float x0f = floorf(gx), y0f = floorf(gy);
        float wx = gx - x0f, wy = gy - y0f;
        int x0 = (int)x0f, y0 = (int)y0f;

        bool vx0 = (unsigned)x0       < (unsigned)HW;
        bool vx1 = (unsigned)(x0 + 1) < (unsigned)HW;
        float Acf = vx0 ? (1.f - wx) : (vx1 ? wx : 0.f);
        float Bcf = (vx0 && vx1) ? wx : 0.f;
        float s0 = ((unsigned)y0       < (unsigned)HW) ? aw * (1.f - wy) : 0.f;
        float s1 = ((unsigned)(y0 + 1) < (unsigned)HW) ? aw * wy : 0.f;

        int xc  = min(max(x0, 0), HW - 1);
        int yc0 = min(max(y0, 0), HW - 1);
        int yc1 = min(max(y0 + 1, 0), HW - 1);
        uint32_t k0 = (uint32_t)(start + yc0 * HW + xc);    // < 65536
        uint32_t k1 = (uint32_t)(start + yc1 * HW + xc);
        KK[t]  = k0 | (k1 << 16);
        CC0[t] = pack2(s0 * Acf, s0 * Bcf);   // half2(CA0, CB0)
        CC1[t] = pack2(s1 * Acf, s1 * Bcf);   // half2(CA1, CB1)
    }

    // pv pointer pre-offset to this lane's 16B word
    const uint4* pvl = pv4 + (h * 8 + j);

    float acc[8] = {0.f, 0.f, 0.f, 0.f, 0.f, 0.f, 0.f, 0.f};

    #pragma unroll
    for (int lvl = 0; lvl < NL; lvl++) {
        __half2 hacc[4];
        #pragma unroll
        for (int i = 0; i < 4; i++) hacc[i] = __floats2half2_rn(0.f, 0.f);

        #pragma unroll
        for (int p = 0; p < NP; p++) {
            const int pt = lvl * 4 + p;
            const int owner = (lane & 24) | (pt >> 1);
            const int t = pt & 1;
            uint32_t kk  = __shfl_sync(0xffffffffu, KK[t],  owner);
            uint32_t c0p = __shfl_sync(0xffffffffu, CC0[t], owner);
            uint32_t c1p = __shfl_sync(0xffffffffu, CC1[t], owner);
            uint32_t c0u = __byte_perm(c0p, c0p, psel);
            uint32_t c1u = __byte_perm(c1p, c1p, psel);
            __half2 c0h = *reinterpret_cast<__half2*>(&c0u);
            __half2 c1h = *reinterpret_cast<__half2*>(&c1u);
            uint4 u0 = pvl[(size_t)(kk & 0xFFFFu) * 64];
            uint4 u1 = pvl[(size_t)(kk >> 16) * 64];
            hacc[0] = __hfma2(*reinterpret_cast<__half2*>(&u0.x), c0h, hacc[0]);
            hacc[1] = __hfma2(*reinterpret_cast<__half2*>(&u0.y), c0h, hacc[1]);
            hacc[2] = __hfma2(*reinterpret_cast<__half2*>(&u0.z), c0h, hacc[2]);
            hacc[3] = __hfma2(*reinterpret_cast<__half2*>(&u0.w), c0h, hacc[3]);
            hacc[0] = __hfma2(*reinterpret_cast<__half2*>(&u1.x), c1h, hacc[0]);
            hacc[1] = __hfma2(*reinterpret_cast<__half2*>(&u1.y), c1h, hacc[1]);
            hacc[2] = __hfma2(*reinterpret_cast<__half2*>(&u1.z), c1h, hacc[2]);
            hacc[3] = __hfma2(*reinterpret_cast<__half2*>(&u1.w), c1h, hacc[3]);
        }
        // drain fp16 level partials into fp32 accumulators
        #pragma unroll
        for (int i = 0; i < 4; i++) {
            float2 f = __half22float2(hacc[i]);
            acc[2 * i + 0] += f.x;
            acc[2 * i + 1] += f.y;
        }
    }

    // combine x0 (lanes j<4) and x1 (lanes j>=4) partial sums
    #pragma unroll
    for (int i = 0; i < 8; i++)
        acc[i] += __shfl_xor_sync(0xffffffffu, acc[i], 4);

    if (isA) {
        uint4 outv;
        outv.x = pack2(acc[0], acc[1]);
        outv.y = pack2(acc[2], acc[3]);
        outv.z = pack2(acc[4], acc[5]);
        outv.w = pack2(acc[6], acc[7]);
        samp4[(size_t)q * 32 + h * 4 + j] = outv;
    }
}

// ---------------- host launch ----------------
static void* sym_addr(const void* sym)
{
    void* p = nullptr;
    cudaGetSymbolAddress(&p, sym);
    return p;
}

extern "C" void kernel_launch(void* const* d_in, const int* in_sizes, int n_in,
                              void* d_out, int out_size)
{
    const float* query     = (const float*)d_in[0];
    const float* query_pos = (const float*)d_in[1];
    const float* value     = (const float*)d_in[2];
    const float* refpts    = (const float*)d_in[3];
    // d_in[4]: spatial_shapes (int32) — compile-time constants here
    const float* W_value   = (const float*)d_in[5];
    const float* b_value   = (const float*)d_in[6];
    const float* W_off     = (const float*)d_in[7];
    const float* b_off     = (const float*)d_in[8];
    const float* W_attn    = (const float*)d_in[9];
    const float* b_attn    = (const float*)d_in[10];
    const float* W_out     = (const float*)d_in[11];
    const float* b_out     = (const float*)d_in[12];
    float* out = (float*)d_out;

    uint32_t* pv     = (uint32_t*)sym_addr(g_pv);
    __half*   oah    = (__half*)sym_addr(g_oah);
    __half*   samph  = (__half*)sym_addr(g_samph);
    __half*   v16    = (__half*)sym_addr(g_v16);
    __half*   q16    = (__half*)sym_addr(g_q16);
    __half*   wv16   = (__half*)sym_addr(g_wv16);
    __half*   wcat16 = (__half*)sym_addr(g_wcat16);
    __half*   wout16 = (__half*)sym_addr(g_wout16);
    float*    bcat   = (float*)sym_addr(g_bcat);

    cudaFuncSetAttribute(gemm_dual,
                         cudaFuncAttributeMaxDynamicSharedMemorySize, GS * STAGE_B);

    // 0) fp16 conversions + weight concat
    {
        int total = 2 * NV8 + 8192 + 12288 + 8192 + 48;
        prep_kernel<<<(total + 255) / 256, 256>>>(
            query, query_pos, value, W_value, W_off, W_attn, W_out,
            b_off, b_attn);
    }
    // 1+2) merged: v = value@Wv^T -> pair buffer (bx 0..3, N=256)
    //              [off|logits] = q@Wcat^T -> oah   (bx 4..9, N=384)
    {
        dim3 grid(4 + 6, NQ / GBM);
        gemm_dual<<<grid, 256, GS * STAGE_B>>>(
            v16, wv16, b_value, 256, pv, nullptr, nullptr, nullptr,
            q16, wcat16, bcat, 384, nullptr, oah, nullptr, nullptr,
            4);
    }
    // 3) deformable sampling (softmax fused) -> samp fp16
    {
        int blocks = (NQ * 2 * 32) / 256;        // 5440, exact
        sample_kernel<<<blocks, 256>>>((const uint4*)pv, refpts, oah,
                                       (uint4*)samph);
    }
    // 4) out = samp @ W_out^T + b_out + query (residual) -> d_out (float)
    {
        dim3 grid(4, NQ / GBM);
        gemm_dual<<<grid, 256, GS * STAGE_B>>>(
            samph, wout16, b_out, 256, nullptr, nullptr, out, query,
            samph, wout16, b_out, 256, nullptr, nullptr, out, query,
            4);
    }
}

// round 17
// speedup vs baseline: 1.0787x; 1.0787x over previous
#include <cuda_runtime.h>
#include <cuda_fp16.h>
#include <math.h>
#include <stdint.h>

// ---------------- problem constants ----------------
#define NQ      21760          // num queries == num keys
#define EMBED   256
#define NH      8
#define NL      4
#define NP      4
#define KDIM    256            // K for all GEMMs

__device__ __constant__ int c_start[NL] = {0, 16384, 20480, 21504};
__device__ __constant__ int c_HW[NL]    = {128, 64, 32, 16};   // square levels

// ---------------- scratch (device globals; no allocations allowed) --------
// x-paired value buffer: per (key, head): [x0: 32ch (64B) | x1: 32ch (64B)].
__device__ uint32_t g_pv   [NQ * 256];
__device__ __half   g_oah  [NQ * 384];   // [offsets(256) | logits(128)] fp16
__device__ __half   g_samph[NQ * 256];   // sampled fp16 (feeds out-GEMM)
__device__ __half   g_v16  [NQ * 256];   // value fp16
__device__ __half   g_q16  [NQ * 256];   // (query+query_pos) fp16
__device__ __half   g_wv16 [256 * 256];  // W_value fp16
__device__ __half   g_wcat16[384 * 256]; // concat W_off;W_attn fp16
__device__ __half   g_wout16[256 * 256]; // W_out fp16
__device__ float    g_bcat [384];        // concat b_off;b_attn fp32

// ---------------- prep: fp16 conversions + weight concat ----------------
__device__ __forceinline__ uint32_t pack2(float x, float y) {
    __half2 h = __floats2half2_rn(x, y);
    return *reinterpret_cast<uint32_t*>(&h);
}
__device__ __forceinline__ uint4 cvt8(const float* s) {
    float4 a = *reinterpret_cast<const float4*>(s);
    float4 b = *reinterpret_cast<const float4*>(s + 4);
    return make_uint4(pack2(a.x,a.y), pack2(a.z,a.w), pack2(b.x,b.y), pack2(b.z,b.w));
}
__device__ __forceinline__ uint4 cvt8sum(const float* s, const float* t) {
    float4 a = *reinterpret_cast<const float4*>(s);
    float4 b = *reinterpret_cast<const float4*>(s + 4);
    float4 c = *reinterpret_cast<const float4*>(t);
    float4 d = *reinterpret_cast<const float4*>(t + 4);
    a.x+=c.x; a.y+=c.y; a.z+=c.z; a.w+=c.w;
    b.x+=d.x; b.y+=d.y; b.z+=d.z; b.w+=d.w;
    return make_uint4(pack2(a.x,a.y), pack2(a.z,a.w), pack2(b.x,b.y), pack2(b.z,b.w));
}

#define NV8 (NQ * 256 / 8)   // 696320

__global__ void __launch_bounds__(256) prep_kernel(
    const float* __restrict__ query, const float* __restrict__ query_pos,
    const float* __restrict__ value,
    const float* __restrict__ Wv, const float* __restrict__ Woff,
    const float* __restrict__ Wattn, const float* __restrict__ Wout,
    const float* __restrict__ boff, const float* __restrict__ battn)
{
    int idx = blockIdx.x * 256 + threadIdx.x;
    const int r0 = NV8;                 // value
    const int r1 = 2 * NV8;             // q
    const int r2 = r1 + 8192;           // Wv
    const int r3 = r2 + 12288;          // Wcat
    const int r4 = r3 + 8192;           // Wout
    const int r5 = r4 + 48;             // bcat

    if (idx < r0) {
        reinterpret_cast<uint4*>(g_v16)[idx] = cvt8(value + (size_t)idx * 8);
    } else if (idx < r1) {
        int i = idx - r0;
        reinterpret_cast<uint4*>(g_q16)[i] =
            cvt8sum(query + (size_t)i * 8, query_pos + (size_t)i * 8);
    } else if (idx < r2) {
        int i = idx - r1;
        reinterpret_cast<uint4*>(g_wv16)[i] = cvt8(Wv + (size_t)i * 8);
    } else if (idx < r3) {
        int i = idx - r2;
        int e = i * 8;
        reinterpret_cast<uint4*>(g_wcat16)[i] =
            (e < 65536) ? cvt8(Woff + e) : cvt8(Wattn + (e - 65536));
    } else if (idx < r4) {
        int i = idx - r3;
        reinterpret_cast<uint4*>(g_wout16)[i] = cvt8(Wout + (size_t)i * 8);
    } else if (idx < r5) {
        int i = idx - r4;
        int e = i * 8;
        #pragma unroll
        for (int jj = 0; jj < 8; jj++) {
            int n = e + jj;
            g_bcat[n] = (n < 256) ? boff[n] : battn[n - 256];
        }
    }
}

// ---------------- fp16 HMMA GEMM, 128x64 tile, cp.async 3-stage ----------
#define GBM 128
#define GBN 64
#define GBK 64
#define GS  3
#define NCH (KDIM / GBK)      // 4
#define STAGE_B 24576         // A 16KB + W 8KB
#define W_OFF   16384

__device__ __forceinline__ void cp16(uint32_t dst, const void* src) {
    asm volatile("cp.async.cg.shared.global [%0], [%1], 16;" :: "r"(dst), "l"(src));
}
__device__ __forceinline__ void cp_commit() {
    asm volatile("cp.async.commit_group;");
}
template <int n>
__device__ __forceinline__ void cp_wait() {
    asm volatile("cp.async.wait_group %0;" :: "n"(n));
}
__device__ __forceinline__ void ldsm_x4a(uint32_t* r, uint32_t addr) {
    asm volatile("ldmatrix.sync.aligned.m8n8.x4.shared.b16 {%0,%1,%2,%3}, [%4];"
                 : "=r"(r[0]), "=r"(r[1]), "=r"(r[2]), "=r"(r[3]) : "r"(addr));
}
__device__ __forceinline__ void mma_f16(float* c, const uint32_t* a,
                                        uint32_t b0, uint32_t b1) {
    asm volatile(
        "mma.sync.aligned.m16n8k16.row.col.f32.f16.f16.f32 "
        "{%0,%1,%2,%3}, {%4,%5,%6,%7}, {%8,%9}, {%0,%1,%2,%3};"
        : "+f"(c[0]), "+f"(c[1]), "+f"(c[2]), "+f"(c[3])
        : "r"(a[0]), "r"(a[1]), "r"(a[2]), "r"(a[3]), "r"(b0), "r"(b1));
}

extern __shared__ __half smx[];

__device__ __forceinline__ uint32_t swadr(uint32_t base, int row, int hc) {
    return base + (uint32_t)(row * 64 + ((hc ^ (row & 7)) << 3)) * 2;
}

__global__ void __launch_bounds__(256, 3) gemm_dual(
    const __half* __restrict__ A0, const __half* __restrict__ W0,
    const float* __restrict__ b0, int N0,
    uint32_t* __restrict__ pair0, __half* __restrict__ h0,
    float* __restrict__ f0, const float* __restrict__ id0,
    const __half* __restrict__ A1, const __half* __restrict__ W1,
    const float* __restrict__ b1, int N1,
    uint32_t* __restrict__ pair1, __half* __restrict__ h1,
    float* __restrict__ f1, const float* __restrict__ id1,
    int split)
{
    int bx = blockIdx.x;
    const int by = blockIdx.y;
    const __half *Ag, *Wg; const float* bias; int N;
    uint32_t* Cpair; __half* Ch; float* Cf; const float* ident;
    if (bx < split) {
        Ag = A0; Wg = W0; bias = b0; N = N0;
        Cpair = pair0; Ch = h0; Cf = f0; ident = id0;
    } else {
        bx -= split;
        Ag = A1; Wg = W1; bias = b1; N = N1;
        Cpair = pair1; Ch = h1; Cf = f1; ident = id1;
    }

    const int tid  = threadIdx.x;
    const int warp = tid >> 5;
    const int lane = tid & 31;
    const int g    = lane >> 2;
    const int tig  = lane & 3;
    const int wm   = (warp >> 1) * 32;   // 4 M-groups of 32
    const int wn   = (warp & 1) * 32;    // 2 N-groups of 32
    const int lrow16 = lane & 15;
    const int lk8    = (lane >> 4) << 3;

    const uint32_t sbase = (uint32_t)__cvta_generic_to_shared(smx);

    const int lr = tid >> 3;     // 0..31
    const int cc = tid & 7;      // 16B chunk in 128B slice
    const __half* Abase = Ag + (size_t)(by * GBM) * KDIM;
    const __half* Wbase = Wg + (size_t)(bx * GBN) * KDIM;

    // PDL: wait for the producer grid before touching its outputs
    cudaGridDependencySynchronize();

    auto load_stage = [&](int st, int kc) {
        const uint32_t sa = sbase + st * STAGE_B;
        const int k0 = kc * GBK;
        #pragma unroll
        for (int r4 = 0; r4 < 4; r4++) {
            int row = r4 * 32 + lr;
            cp16(swadr(sa, row, cc), Abase + (size_t)row * KDIM + k0 + cc * 8);
        }
        #pragma unroll
        for (int r2 = 0; r2 < 2; r2++) {
            int row = r2 * 32 + lr;
            cp16(swadr(sa + W_OFF, row, cc), Wbase + (size_t)row * KDIM + k0 + cc * 8);
        }
        cp_commit();
    };

    float acc[2][4][4];
    #pragma unroll
    for (int i = 0; i < 2; i++)
        #pragma unroll
        for (int jx = 0; jx < 4; jx++)
            #pragma unroll
            for (int t = 0; t < 4; t++) acc[i][jx][t] = 0.f;

    load_stage(0, 0);
    load_stage(1, 1);

    #pragma unroll
    for (int i = 0; i < NCH; i++) {
        if (i < NCH - 1) cp_wait<1>(); else cp_wait<0>();
        __syncthreads();
        const int st = i % GS;
        const uint32_t sa = sbase + st * STAGE_B;

        #pragma unroll
        for (int kk = 0; kk < GBK; kk += 16) {
            const int hc = (kk + lk8) >> 3;
            uint32_t af[2][4];
            #pragma unroll
            for (int mf = 0; mf < 2; mf++)
                ldsm_x4a(af[mf], swadr(sa, wm + mf * 16 + lrow16, hc));
            uint32_t bf[4][2];
            #pragma unroll
            for (int g4 = 0; g4 < 2; g4++) {
                uint32_t r[4];
                ldsm_x4a(r, swadr(sa + W_OFF, wn + g4 * 16 + lrow16, hc));
                bf[g4 * 2 + 0][0] = r[0]; bf[g4 * 2 + 0][1] = r[2];
                bf[g4 * 2 + 1][0] = r[1]; bf[g4 * 2 + 1][1] = r[3];
            }
            #pragma unroll
            for (int mf = 0; mf < 2; mf++)
                #pragma unroll
                for (int nf = 0; nf < 4; nf++)
                    mma_f16(acc[mf][nf], af[mf], bf[nf][0], bf[nf][1]);
        }
        if (i + GS - 1 < NCH) load_stage((i + GS - 1) % GS, i + GS - 1);
    }

    // PDL: mainloop done — allow dependent grid to start spinning up
    cudaTriggerProgrammaticLaunchCompletion();

    // ---------------- epilogue ----------------
    const int nb = bx * GBN + wn;
    if (Cpair) {
        // staged coalesced pair epilogue: pack to smem (pitch 36 words), then
        // write x0/x1 64B groups with 4 lanes each (full-sector stores).
        uint32_t* stg = reinterpret_cast<uint32_t*>(smx);
        __syncthreads();   // pipeline smem now dead for all warps
        #pragma unroll
        for (int mf = 0; mf < 2; mf++) {
            #pragma unroll
            for (int hh = 0; hh < 2; hh++) {
                int ml = wm + mf * 16 + g + hh * 8;
                #pragma unroll
                for (int nf = 0; nf < 4; nf++) {
                    int col = nb + nf * 8 + tig * 2;   // within N (bias idx)
                    float2 bb = *reinterpret_cast<const float2*>(bias + col);
                    float rx = acc[mf][nf][hh * 2 + 0] + bb.x;
                    float ry = acc[mf][nf][hh * 2 + 1] + bb.y;
                    int cl = (wn + nf * 8 + tig * 2) >> 1;   // 0..31 pair idx
                    stg[ml * 36 + cl] = pack2(rx, ry);
                }
            }
        }
        __syncthreads();
        #pragma unroll
        for (int ro = 0; ro < 4; ro++) {
            int gid  = ro * 64 + (tid >> 2);   // 0..255: (m row, hd half)
            int part = tid & 3;
            int ml = gid >> 1, hdl = gid & 1;
            uint4 val = *reinterpret_cast<uint4*>(&stg[ml * 36 + hdl * 16 + part * 4]);
            int mg = by * GBM + ml;
            int hd = bx * 2 + hdl;
            reinterpret_cast<uint4*>(Cpair + ((size_t)mg * 8 + hd) * 32)[part] = val;
            if (mg > 0)
                reinterpret_cast<uint4*>(
                    Cpair + ((size_t)(mg - 1) * 8 + hd) * 32 + 16)[part] = val;
        }
    } else {
        #pragma unroll
        for (int mf = 0; mf < 2; mf++) {
            #pragma unroll
            for (int hh = 0; hh < 2; hh++) {
                int m = by * GBM + wm + mf * 16 + g + hh * 8;
                #pragma unroll
                for (int nf = 0; nf < 4; nf++) {
                    int col = nb + nf * 8 + tig * 2;
                    float2 bb = *reinterpret_cast<const float2*>(bias + col);
                    float2 r;
                    r.x = acc[mf][nf][hh * 2 + 0] + bb.x;
                    r.y = acc[mf][nf][hh * 2 + 1] + bb.y;
                    if (ident) {
                        float2 iv = *reinterpret_cast<const float2*>(
                            ident + (size_t)m * N + col);
                        r.x += iv.x; r.y += iv.y;
                    }
                    if (Ch) {
                        *reinterpret_cast<__half2*>(Ch + (size_t)m * N + col) =
                            __floats2half2_rn(r.x, r.y);
                    } else {
                        *reinterpret_cast<float2*>(Cf + (size_t)m * N + col) = r;
                    }
                }
            }
        }
    }
}

// ---------------- deformable sampling + fused softmax ----------------
// Warp per (q, head-quad): 8 lanes/head; j<4 accumulate x0-slot, j>=4 x1-slot.
// Lane j owns points 2j, 2j+1. Packed broadcasts: keys (k0|k1<<16) in one u32,
// coefficient (CA,CB) pairs as half2 — 3 shuffles + 2 PRMT per point.
// Inner accumulation in fp16 (HFMA2), drained to fp32 once per level.
__global__ void __launch_bounds__(256) sample_kernel(
    const uint4* __restrict__ pv4, const float* __restrict__ ref,
    const __half* __restrict__ oah, uint4* __restrict__ samp4)
{
    const int gwarp = (blockIdx.x * blockDim.x + threadIdx.x) >> 5;
    const int lane = threadIdx.x & 31;
    if (gwarp >= NQ * 2) return;
    const int q  = gwarp >> 1;
    const int hq = gwarp & 1;
    const int h4 = lane >> 3;
    const int j  = lane & 7;
    const int h  = hq * 4 + h4;
    const bool isA = (j < 4);
    const uint32_t psel = isA ? 0x1010u : 0x3232u;   // PRMT: replicate lo/hi half

    // PDL: wait for g1 (pv + oah producers) before first dependent load
    cudaGridDependencySynchronize();

    uint2 ov = *reinterpret_cast<const uint2*>(oah + (size_t)q * 384 + h * 32 + j * 4);
    float2 o0 = __half22float2(*reinterpret_cast<__half2*>(&ov.x));
    float2 o1 = __half22float2(*reinterpret_cast<__half2*>(&ov.y));
    uint32_t lvu = *reinterpret_cast<const uint32_t*>(
        oah + (size_t)q * 384 + 256 + h * 16 + j * 2);
    float2 lg = __half22float2(*reinterpret_cast<__half2*>(&lvu));

    float mx = fmaxf(lg.x, lg.y);
    mx = fmaxf(mx, __shfl_xor_sync(0xffffffffu, mx, 1));
    mx = fmaxf(mx, __shfl_xor_sync(0xffffffffu, mx, 2));
    mx = fmaxf(mx, __shfl_xor_sync(0xffffffffu, mx, 4));
    float e0 = __expf(lg.x - mx), e1 = __expf(lg.y - mx);
    float s = e0 + e1;
    s += __shfl_xor_sync(0xffffffffu, s, 1);
    s += __shfl_xor_sync(0xffffffffu, s, 2);
    s += __shfl_xor_sync(0xffffffffu, s, 4);
    float inv = 1.f / s;
    float w0 = e0 * inv, w1 = e1 * inv;

    // owner precompute for owned points 2j (t=0), 2j+1 (t=1)
    uint32_t KK[2], CC0[2], CC1[2];
    #pragma unroll
    for (int t = 0; t < 2; t++) {
        int ptm = 2 * j + t;
        int lvl = ptm >> 2;
        int HW = c_HW[lvl];
        int start = c_start[lvl];
        float fHW = (float)HW;
        float rx = ref[(size_t)q * 8 + lvl * 2 + 0];
        float ry = ref[(size_t)q * 8 + lvl * 2 + 1];
        float ox = t ? o1.x : o0.x;
        float oy = t ? o1.y : o0.y;
        float aw = t ? w1 : w0;

        float gx = fmaf(rx, fHW, ox - 0.5f);
        float gy = fmaf(ry, fHW, oy - 0.5f);
        float x0f = floorf(gx), y0f = floorf(gy);
        float wx = gx - x0f, wy = gy - y0f;
        int x0 = (int)x0f, y0 = (int)y0f;

        bool vx0 = (unsigned)x0       < (unsigned)HW;
        bool vx1 = (unsigned)(x0 + 1) < (unsigned)HW;
        float Acf = vx0 ? (1.f - wx) : (vx1 ? wx : 0.f);
        float Bcf = (vx0 && vx1) ? wx : 0.f;
        float s0 = ((unsigned)y0       < (unsigned)HW) ? aw * (1.f - wy) : 0.f;
        float s1 = ((unsigned)(y0 + 1) < (unsigned)HW) ? aw * wy : 0.f;

        int xc  = min(max(x0, 0), HW - 1);
        int yc0 = min(max(y0, 0), HW - 1);
        int yc1 = min(max(y0 + 1, 0), HW - 1);
        uint32_t k0 = (uint32_t)(start + yc0 * HW + xc);    // < 65536
        uint32_t k1 = (uint32_t)(start + yc1 * HW + xc);
        KK[t]  = k0 | (k1 << 16);
        CC0[t] = pack2(s0 * Acf, s0 * Bcf);   // half2(CA0, CB0)
        CC1[t] = pack2(s1 * Acf, s1 * Bcf);   // half2(CA1, CB1)
    }

    // pv pointer pre-offset to this lane's 16B word
    const uint4* pvl = pv4 + (h * 8 + j);

    float acc[8] = {0.f, 0.f, 0.f, 0.f, 0.f, 0.f, 0.f, 0.f};

    #pragma unroll
    for (int lvl = 0; lvl < NL; lvl++) {
        __half2 hacc[4];
        #pragma unroll
        for (int i = 0; i < 4; i++) hacc[i] = __floats2half2_rn(0.f, 0.f);

        #pragma unroll
        for (int p = 0; p < NP; p++) {
            const int pt = lvl * 4 + p;
            const int owner = (lane & 24) | (pt >> 1);
            const int t = pt & 1;
            uint32_t kk  = __shfl_sync(0xffffffffu, KK[t],  owner);
            uint32_t c0p = __shfl_sync(0xffffffffu, CC0[t], owner);
            uint32_t c1p = __shfl_sync(0xffffffffu, CC1[t], owner);
            uint32_t c0u = __byte_perm(c0p, c0p, psel);
            uint32_t c1u = __byte_perm(c1p, c1p, psel);
            __half2 c0h = *reinterpret_cast<__half2*>(&c0u);
            __half2 c1h = *reinterpret_cast<__half2*>(&c1u);
            uint4 u0 = pvl[(size_t)(kk & 0xFFFFu) * 64];
            uint4 u1 = pvl[(size_t)(kk >> 16) * 64];
            hacc[0] = __hfma2(*reinterpret_cast<__half2*>(&u0.x), c0h, hacc[0]);
            hacc[1] = __hfma2(*reinterpret_cast<__half2*>(&u0.y), c0h, hacc[1]);
            hacc[2] = __hfma2(*reinterpret_cast<__half2*>(&u0.z), c0h, hacc[2]);
            hacc[3] = __hfma2(*reinterpret_cast<__half2*>(&u0.w), c0h, hacc[3]);
            hacc[0] = __hfma2(*reinterpret_cast<__half2*>(&u1.x), c1h, hacc[0]);
            hacc[1] = __hfma2(*reinterpret_cast<__half2*>(&u1.y), c1h, hacc[1]);
            hacc[2] = __hfma2(*reinterpret_cast<__half2*>(&u1.z), c1h, hacc[2]);
            hacc[3] = __hfma2(*reinterpret_cast<__half2*>(&u1.w), c1h, hacc[3]);
        }
        // drain fp16 level partials into fp32 accumulators
        #pragma unroll
        for (int i = 0; i < 4; i++) {
            float2 f = __half22float2(hacc[i]);
            acc[2 * i + 0] += f.x;
            acc[2 * i + 1] += f.y;
        }
    }

    // PDL: gather loop done — allow g2 to start spinning up
    cudaTriggerProgrammaticLaunchCompletion();

    // combine x0 (lanes j<4) and x1 (lanes j>=4) partial sums
    #pragma unroll
    for (int i = 0; i < 8; i++)
        acc[i] += __shfl_xor_sync(0xffffffffu, acc[i], 4);

    if (isA) {
        uint4 outv;
        outv.x = pack2(acc[0], acc[1]);
        outv.y = pack2(acc[2], acc[3]);
        outv.z = pack2(acc[4], acc[5]);
        outv.w = pack2(acc[6], acc[7]);
        samp4[(size_t)q * 32 + h * 4 + j] = outv;
    }
}

// ---------------- host launch ----------------
static void* sym_addr(const void* sym)
{
    void* p = nullptr;
    cudaGetSymbolAddress(&p, sym);
    return p;
}

extern "C" void kernel_launch(void* const* d_in, const int* in_sizes, int n_in,
                              void* d_out, int out_size)
{
    const float* query     = (const float*)d_in[0];
    const float* query_pos = (const float*)d_in[1];
    const float* value     = (const float*)d_in[2];
    const float* refpts    = (const float*)d_in[3];
    // d_in[4]: spatial_shapes (int32) — compile-time constants here
    const float* W_value   = (const float*)d_in[5];
    const float* b_value   = (const float*)d_in[6];
    const float* W_off     = (const float*)d_in[7];
    const float* b_off     = (const float*)d_in[8];
    const float* W_attn    = (const float*)d_in[9];
    const float* b_attn    = (const float*)d_in[10];
    const float* W_out     = (const float*)d_in[11];
    const float* b_out     = (const float*)d_in[12];
    float* out = (float*)d_out;

    uint32_t* pv     = (uint32_t*)sym_addr(g_pv);
    __half*   oah    = (__half*)sym_addr(g_oah);
    __half*   samph  = (__half*)sym_addr(g_samph);
    __half*   v16    = (__half*)sym_addr(g_v16);
    __half*   q16    = (__half*)sym_addr(g_q16);
    __half*   wv16   = (__half*)sym_addr(g_wv16);
    __half*   wcat16 = (__half*)sym_addr(g_wcat16);
    __half*   wout16 = (__half*)sym_addr(g_wout16);
    float*    bcat   = (float*)sym_addr(g_bcat);

    cudaFuncSetAttribute(gemm_dual,
                         cudaFuncAttributeMaxDynamicSharedMemorySize, GS * STAGE_B);

    // PDL launch attribute (consumers synchronize in-kernel)
    cudaLaunchAttribute pdlAttr[1];
    pdlAttr[0].id = cudaLaunchAttributeProgrammaticStreamSerialization;
    pdlAttr[0].val.programmaticStreamSerializationAllowed = 1;

    // 0) fp16 conversions + weight concat (plain launch)
    {
        int total = 2 * NV8 + 8192 + 12288 + 8192 + 48;
        prep_kernel<<<(total + 255) / 256, 256>>>(
            query, query_pos, value, W_value, W_off, W_attn, W_out,
            b_off, b_attn);
    }
    // 1+2) merged: v = value@Wv^T -> pair buffer (bx 0..3, N=256)
    //              [off|logits] = q@Wcat^T -> oah   (bx 4..9, N=384)
    {
        cudaLaunchConfig_t cfg = {};
        cfg.gridDim  = dim3(4 + 6, NQ / GBM);
        cfg.blockDim = dim3(256);
        cfg.dynamicSmemBytes = GS * STAGE_B;
        cfg.attrs = pdlAttr;
        cfg.numAttrs = 1;
        cudaLaunchKernelEx(&cfg, gemm_dual,
            (const __half*)v16, (const __half*)wv16, b_value, 256,
            pv, (__half*)nullptr, (float*)nullptr, (const float*)nullptr,
            (const __half*)q16, (const __half*)wcat16, (const float*)bcat, 384,
            (uint32_t*)nullptr, oah, (float*)nullptr, (const float*)nullptr,
            4);
    }
    // 3) deformable sampling (softmax fused) -> samp fp16
    {
        cudaLaunchConfig_t cfg = {};
        cfg.gridDim  = dim3((NQ * 2 * 32) / 256);   // 5440, exact
        cfg.blockDim = dim3(256);
        cfg.attrs = pdlAttr;
        cfg.numAttrs = 1;
        cudaLaunchKernelEx(&cfg, sample_kernel,
            (const uint4*)pv, refpts, (const __half*)oah, (uint4*)samph);
    }
    // 4) out = samp @ W_out^T + b_out + query (residual) -> d_out (float)
    {
        cudaLaunchConfig_t cfg = {};
        cfg.gridDim  = dim3(4, NQ / GBM);
        cfg.blockDim = dim3(256);
        cfg.dynamicSmemBytes = GS * STAGE_B;
        cfg.attrs = pdlAttr;
        cfg.numAttrs = 1;
        cudaLaunchKernelEx(&cfg, gemm_dual,
            (const __half*)samph, (const __half*)wout16, b_out, 256,
            (uint32_t*)nullptr, (__half*)nullptr, out, query,
            (const __half*)samph, (const __half*)wout16, b_out, 256,
            (uint32_t*)nullptr, (__half*)nullptr, out, query,
            4);
    }
}